// round 16
// baseline (speedup 1.0000x reference)
#include <cuda_runtime.h>
#include <cuda_fp16.h>
#include <math.h>
#include <stdint.h>

#define NPTS  65536
#define NV    512
#define KNN   8
#define HID   512
#define F0V   1563          // (V+1)*3 + 3*K
#define FIV   2075          // F0 + H
#define KP    1600          // F0 padded to /64 (and /32 for transpose tiles)
#define NC    2048          // 4*H packed first-layer columns
#define ROWIN 1539          // 3 + 3*V
#define NLAY  11            // chained 512x512 GEMMs
#define SA    72            // smem row stride in halfs (64 + 8 pad)

#define ABYTES  (128 * SA * 2)              // 18432
#define STAGE_B (2 * ABYTES)                // 36864
#define TC_SMEM (3 * STAGE_B)               // 110592 -> 2 CTAs/SM

// ---- static scratch ----
__device__ __align__(128) __half g_X  [(size_t)NPTS * KP];
__device__ __align__(128) float  g_P  [(size_t)NPTS * NC];
__device__ __align__(128) __half g_R  [(size_t)NPTS * HID];
__device__ __align__(128) __half g_WcT[(size_t)NC * KP];
__device__ __align__(128) __half g_BT [(size_t)NLAY * HID * HID];
__device__ __align__(128) float  g_bc [NC];
__device__ __align__(128) __half g_A0 [(size_t)NPTS * HID];
__device__ __align__(128) __half g_A1 [(size_t)NPTS * HID];

// ---------------- helpers ----------------
__device__ __forceinline__ uint32_t smem_u32(const void* p) {
    uint32_t a;
    asm("{ .reg .u64 t; cvta.to.shared.u64 t, %1; cvt.u32.u64 %0, t; }" : "=r"(a) : "l"(p));
    return a;
}
#define CP_ASYNC16(dst, src) \
    asm volatile("cp.async.cg.shared.global [%0], [%1], 16;" :: "r"(dst), "l"(src))

#define LDM_X4(r0, r1, r2, r3, addr) \
    asm("ldmatrix.sync.aligned.m8n8.x4.shared.b16 {%0,%1,%2,%3}, [%4];" \
        : "=r"(r0), "=r"(r1), "=r"(r2), "=r"(r3) : "r"(addr) : "memory")

__device__ __forceinline__ void mma16816(float* c, const uint32_t* a, const uint32_t* b) {
    asm("mma.sync.aligned.m16n8k16.row.col.f32.f16.f16.f32 "
        "{%0,%1,%2,%3}, {%4,%5,%6,%7}, {%8,%9}, {%0,%1,%2,%3};"
        : "+f"(c[0]), "+f"(c[1]), "+f"(c[2]), "+f"(c[3])
        : "r"(a[0]), "r"(a[1]), "r"(a[2]), "r"(a[3]), "r"(b[0]), "r"(b[1]));
}

// ---------------------------------------------------------------------------
// Stage 0: warp-per-row 8-NN (shfl-only) + sync-free latent copy
// ---------------------------------------------------------------------------
__global__ void __launch_bounds__(256)
build_x_kernel(const float* __restrict__ cxyz) {
    const int warp = threadIdx.x >> 5, lane = threadIdx.x & 31;
    const int rowBase = blockIdx.x * 8;

    for (int e = threadIdx.x; e < 8 * 3 * NV; e += 256) {
        int rl = e / (3 * NV), j = e % (3 * NV);
        g_X[(size_t)(rowBase + rl) * KP + 27 + j] =
            __float2half_rn(cxyz[(size_t)(rowBase + rl) * ROWIN + 3 + j]);
    }

    const int row = rowBase + warp;
    const float* cr = cxyz + (size_t)row * ROWIN;
    const float x = cr[0], y = cr[1], z = cr[2];

    float d2[16];
#pragma unroll
    for (int j = 0; j < 16; j++) {
        int g = lane + 32 * j;
        float dx = x - cr[3 + 3 * g], dy = y - cr[4 + 3 * g], dz = z - cr[5 + 3 * g];
        d2[j] = dx * dx + dy * dy + dz * dz;
    }

    int idx8[KNN];
#pragma unroll
    for (int s = 0; s < KNN; s++) {
        float bv = INFINITY; int bj = 0;
#pragma unroll
        for (int j = 0; j < 16; j++)
            if (d2[j] < bv) { bv = d2[j]; bj = j; }
        int bidx = lane + 32 * bj;
#pragma unroll
        for (int o = 16; o > 0; o >>= 1) {
            float ov = __shfl_xor_sync(0xffffffffu, bv, o);
            int   oi = __shfl_xor_sync(0xffffffffu, bidx, o);
            if (ov < bv || (ov == bv && oi < bidx)) { bv = ov; bidx = oi; }
        }
        idx8[s] = bidx;
        if ((bidx & 31) == lane) d2[bidx >> 5] = INFINITY;
    }

    __half* xr = g_X + (size_t)row * KP;
    if (lane < 3) xr[lane] = __float2half_rn(cr[lane]);
    if (lane >= 3 && lane < 27) {
        int t = lane - 3;
        xr[lane] = __float2half_rn(cr[3 + 3 * idx8[t / 3] + (t % 3)]);
    }
    for (int t = F0V + lane; t < KP; t += 32) xr[t] = __float2half_rn(0.f);
}

// ---------------------------------------------------------------------------
// Tiled-transpose weight packing (coalesced read AND write via 32x33 smem)
// ---------------------------------------------------------------------------
// g_WcT[n*KP + k] = S(k, n);  S read contiguous in n (h-contiguous sources).
__global__ void __launch_bounds__(256)
pack_wcT_kernel(const float* __restrict__ Wf, const float* __restrict__ Win) {
    __shared__ float tile[32][33];
    const int k0 = blockIdx.x * 32;          // KP/32 = 50 tiles
    const int n0 = blockIdx.y * 32;          // NC/32 = 64 tiles
    const int tx = threadIdx.x & 31, ty = threadIdx.x >> 5;   // 32 x 8
    const int blk = n0 >> 9;                 // 32-wide n-tile stays in one block
#pragma unroll
    for (int i = 0; i < 4; i++) {
        int k = k0 + ty + i * 8;
        int h = (n0 & 511) + tx;
        float v = 0.f;
        if (k < F0V) {
            if (blk == 0) v = Wf[(size_t)k * HID + h];
            else          v = Win[(size_t)(blk - 1) * FIV * HID + (size_t)(HID + k) * HID + h];
        }
        tile[ty + i * 8][tx] = v;
    }
    __syncthreads();
#pragma unroll
    for (int i = 0; i < 4; i++) {
        int n = n0 + ty + i * 8;
        g_WcT[(size_t)n * KP + k0 + tx] = __float2half_rn(tile[tx][ty + i * 8]);
    }
}

// g_BT[i][n][k] = W(i)(k, n); W read contiguous in n.
__global__ void __launch_bounds__(256)
pack_bt_kernel(const float* __restrict__ Wh, const float* __restrict__ Win) {
    __shared__ float tile[32][33];
    const int i  = blockIdx.z;
    const int k0 = blockIdx.x * 32;          // HID/32 = 16
    const int n0 = blockIdx.y * 32;
    const int tx = threadIdx.x & 31, ty = threadIdx.x >> 5;
    const float* src;
    if (i % 3 == 2) { int b = i / 3 + 1; src = Win + (size_t)(b - 1) * FIV * HID; }
    else            { int b = i / 3, l = i % 3; src = Wh + (size_t)(b * 2 + l) * HID * HID; }
#pragma unroll
    for (int t = 0; t < 4; t++) {
        int k = k0 + ty + t * 8;
        tile[ty + t * 8][tx] = src[(size_t)k * HID + n0 + tx];
    }
    __syncthreads();
    __half* dst = g_BT + (size_t)i * HID * HID;
#pragma unroll
    for (int t = 0; t < 4; t++) {
        int n = n0 + ty + t * 8;
        dst[(size_t)n * HID + k0 + tx] = __float2half_rn(tile[tx][ty + t * 8]);
    }
}

__global__ void pack_b_kernel(const float* __restrict__ bf, const float* __restrict__ bin) {
    int j = blockIdx.x * blockDim.x + threadIdx.x;
    if (j < NC) {
        int blk = j >> 9, h = j & 511;
        g_bc[j] = (blk == 0) ? bf[h] : bin[(blk - 1) * HID + h];
    }
}

// ---------------------------------------------------------------------------
// fp16 mma.sync GEMM: Y = act(A @ Bt^T + addend)
//   CTA 128x128, BK=64, 8 warps (2m x 4n), warp tile 64x32, 3-stage cp.async.
//   Bulk LDSM schedule (R13) + strength-reduced addressing (R14) + kk rotation.
// ---------------------------------------------------------------------------
__global__ void __launch_bounds__(256, 2)
hgemm(const __half* __restrict__ A, int lda,
      const __half* __restrict__ Bt, int ldb,
      const float* __restrict__ addp, int addIsMat, int ldadd,
      void* __restrict__ Yv, int ldy, int outF32,
      __half* __restrict__ Y2,
      int nk, int doRelu)
{
    extern __shared__ __align__(16) char smem[];
    const uint32_t sbase = smem_u32(smem);
    const int tid = threadIdx.x;
    const int m0 = blockIdx.y * 128, n0 = blockIdx.x * 128;
    const int w = tid >> 5, lane = tid & 31;
    const int wm = (w >> 2) * 64, wn = (w & 3) * 32;
    const int kkStart = ((w & 3) + ((w >> 2) << 1)) & 3;

    // strength-reduced cp.async addressing
    const int cA = tid & 7;
    const int rA = tid >> 3;
    __uint64_t gA = (__uint64_t)(A  + (size_t)(m0 + rA) * lda + cA * 8);
    __uint64_t gB = (__uint64_t)(Bt + (size_t)(n0 + rA) * ldb + cA * 8);
    const __uint64_t strideA = (__uint64_t)32 * lda * 2;
    const __uint64_t strideB = (__uint64_t)32 * ldb * 2;
    uint32_t dstA = sbase + rA * (SA * 2) + cA * 16;
    uint32_t dstB = sbase + ABYTES + rA * (SA * 2) + cA * 16;
    const uint32_t dstStride = 32 * (SA * 2);

    float acc[4][4][4];
#pragma unroll
    for (int i = 0; i < 4; i++)
#pragma unroll
        for (int j = 0; j < 4; j++)
#pragma unroll
            for (int t = 0; t < 4; t++) acc[i][j][t] = 0.f;

    auto load_tile = [&](int s) {
        if (s < nk) {
            uint32_t so = (uint32_t)((s % 3) * STAGE_B);
            __uint64_t a = gA + (__uint64_t)s * 128;
            __uint64_t b = gB + (__uint64_t)s * 128;
#pragma unroll
            for (int i = 0; i < 4; i++)
                CP_ASYNC16(dstA + so + i * dstStride, (const void*)(a + i * strideA));
#pragma unroll
            for (int i = 0; i < 4; i++)
                CP_ASYNC16(dstB + so + i * dstStride, (const void*)(b + i * strideB));
        }
        asm volatile("cp.async.commit_group;" ::: "memory");
    };

    load_tile(0);
    load_tile(1);

    const uint32_t lmOff = (uint32_t)((lane & 15) * (SA * 2) + (lane >> 4) * 16);
    uint32_t aBs[3], bBs[3];
#pragma unroll
    for (int st = 0; st < 3; st++) {
        aBs[st] = sbase + st * STAGE_B + wm * (SA * 2) + lmOff;
        bBs[st] = sbase + st * STAGE_B + ABYTES + wn * (SA * 2) + lmOff;
    }

    for (int s = 0; s < nk; ++s) {
        asm volatile("cp.async.wait_group 1;" ::: "memory");
        __syncthreads();
        load_tile(s + 2);

        const int st = s % 3;
        const uint32_t aB = aBs[st], bB = bBs[st];
#pragma unroll
        for (int kq = 0; kq < 4; kq++) {
            const int kk = (kq + kkStart) & 3;
            const uint32_t ko = kk * 32;
            uint32_t aF[4][4], bF[4][2];
            // bulk schedule (R13 best): dep-first loads, then full MMA sweep
            LDM_X4(aF[0][0], aF[0][1], aF[0][2], aF[0][3], aB + ko);
            LDM_X4(bF[0][0], bF[1][0], bF[0][1], bF[1][1], bB + ko);
            LDM_X4(bF[2][0], bF[3][0], bF[2][1], bF[3][1], bB + 16 * SA * 2 + ko);
            LDM_X4(aF[1][0], aF[1][1], aF[1][2], aF[1][3], aB + 1 * (16 * SA * 2) + ko);
            LDM_X4(aF[2][0], aF[2][1], aF[2][2], aF[2][3], aB + 2 * (16 * SA * 2) + ko);
            LDM_X4(aF[3][0], aF[3][1], aF[3][2], aF[3][3], aB + 3 * (16 * SA * 2) + ko);
#pragma unroll
            for (int mt = 0; mt < 4; mt++)
#pragma unroll
                for (int nt = 0; nt < 4; nt++)
                    mma16816(acc[mt][nt], aF[mt], bF[nt]);
        }
    }

    // ---- epilogue ----
    float*  Yf = (float*)Yv;
    __half* Yh = (__half*)Yv;
#pragma unroll
    for (int mt = 0; mt < 4; mt++) {
#pragma unroll
        for (int nt = 0; nt < 4; nt++) {
            const float* c = acc[mt][nt];
            int r0 = m0 + wm + mt * 16 + (lane >> 2);
            int cc = n0 + wn + nt * 8 + (lane & 3) * 2;
#pragma unroll
            for (int h = 0; h < 2; h++) {
                int r = r0 + h * 8;
                float v0 = c[2 * h + 0], v1 = c[2 * h + 1];
                if (addIsMat) {
                    float2 a2 = *(const float2*)(addp + (size_t)r * ldadd + cc);
                    v0 += a2.x; v1 += a2.y;
                } else {
                    v0 += addp[cc]; v1 += addp[cc + 1];
                }
                if (doRelu) { v0 = fmaxf(v0, 0.f); v1 = fmaxf(v1, 0.f); }
                if (outF32) {
                    *(float2*)(Yf + (size_t)r * ldy + cc) = make_float2(v0, v1);
                    if (Y2 != nullptr && cc < HID) {
                        __half2 hv = __floats2half2_rn(fmaxf(v0, 0.f), fmaxf(v1, 0.f));
                        *(__half2*)(Y2 + (size_t)r * HID + cc) = hv;
                    }
                } else {
                    *(__half2*)(Yh + (size_t)r * ldy + cc) = __floats2half2_rn(v0, v1);
                }
            }
        }
    }
}

// ---------------------------------------------------------------------------
// Output: out[row] = tanh(dot(x, W_out) + b_out)
// ---------------------------------------------------------------------------
__global__ void out_kernel(const __half* __restrict__ Xin, const float* __restrict__ Wo,
                           const float* __restrict__ bo, float* __restrict__ out) {
    const int row  = blockIdx.x * 8 + (threadIdx.x >> 5);
    const int lane = threadIdx.x & 31;
    const __half2* xr = (const __half2*)(Xin + (size_t)row * HID);
    float s = 0.f;
#pragma unroll 4
    for (int j = lane; j < HID / 2; j += 32) {
        float2 v = __half22float2(xr[j]);
        s += v.x * Wo[2 * j] + v.y * Wo[2 * j + 1];
    }
#pragma unroll
    for (int o = 16; o > 0; o >>= 1) s += __shfl_xor_sync(0xffffffffu, s, o);
    if (lane == 0) out[row] = tanhf(s + bo[0]);
}

// ---------------------------------------------------------------------------
extern "C" void kernel_launch(void* const* d_in, const int* in_sizes, int n_in,
                              void* d_out, int out_size) {
    const float* cxyz = (const float*)d_in[0];
    const float* Wf   = (const float*)d_in[1];
    const float* bf   = (const float*)d_in[2];
    const float* Win  = (const float*)d_in[3];
    const float* bin  = (const float*)d_in[4];
    const float* Wh   = (const float*)d_in[5];
    const float* bh   = (const float*)d_in[6];
    const float* Wo   = (const float*)d_in[7];
    const float* bo   = (const float*)d_in[8];
    float* out = (float*)d_out;

    __half *X, *R, *WcT, *BT, *A0, *A1;
    float *P, *bc;
    cudaGetSymbolAddress((void**)&X,   g_X);
    cudaGetSymbolAddress((void**)&P,   g_P);
    cudaGetSymbolAddress((void**)&R,   g_R);
    cudaGetSymbolAddress((void**)&WcT, g_WcT);
    cudaGetSymbolAddress((void**)&BT,  g_BT);
    cudaGetSymbolAddress((void**)&bc,  g_bc);
    cudaGetSymbolAddress((void**)&A0,  g_A0);
    cudaGetSymbolAddress((void**)&A1,  g_A1);

    cudaFuncSetAttribute(hgemm, cudaFuncAttributeMaxDynamicSharedMemorySize, TC_SMEM);

    // Launch order arranged so the BIG hgemm is the 4th launch (ncu samples #4).
    build_x_kernel<<<NPTS / 8, 256>>>(cxyz);
    {
        dim3 g(KP / 32, NC / 32);
        pack_wcT_kernel<<<g, 256>>>(Wf, Win);
    }
    pack_b_kernel<<<8, 256>>>(bf, bin);

    // Big GEMM: P = x_ @ Wcat + bcat (f32 out); also R = relu(P[:, :512]) fp16
    dim3 gBig(NC / 128, NPTS / 128);
    hgemm<<<gBig, 256, TC_SMEM>>>(X, KP, WcT, KP, bc, 0, 0, P, NC, 1, R, KP / 64, 0);

    {
        dim3 g(HID / 32, HID / 32, NLAY);
        pack_bt_kernel<<<g, 256>>>(Wh, Win);
    }

    // Chain of 11 GEMMs (fp16 activations)
    dim3 gL(HID / 128, NPTS / 128);
    const __half* a_in = R;
    __half* outs[2] = { A0, A1 };
    int pp = 0;
    for (int i = 0; i < NLAY; i++) {
        const __half* Bl = BT + (size_t)i * HID * HID;
        const float* addp;
        int addIsMat, ldadd;
        if (i % 3 == 2) {
            int b = i / 3 + 1;
            addp = P + (size_t)b * HID; addIsMat = 1; ldadd = NC;
        } else {
            int b = i / 3, l = i % 3;
            addp = bh + (size_t)(b * 2 + l) * HID; addIsMat = 0; ldadd = 0;
        }
        __half* y = outs[pp];
        hgemm<<<gL, 256, TC_SMEM>>>(a_in, HID, Bl, HID, addp, addIsMat, ldadd,
                                    y, HID, 0, nullptr, HID / 64, 1);
        a_in = y;
        pp ^= 1;
    }

    out_kernel<<<NPTS / 8, 256>>>(a_in, Wo, bo, out);
}

// round 17
// speedup vs baseline: 1.5703x; 1.5703x over previous
#include <cuda_runtime.h>
#include <cuda_fp16.h>
#include <math.h>
#include <stdint.h>

#define NPTS  65536
#define NV    512
#define KNN   8
#define HID   512
#define F0V   1563          // (V+1)*3 + 3*K
#define FIV   2075          // F0 + H
#define KP    1600          // F0 padded to /64
#define NC    2048          // 4*H packed first-layer columns
#define ROWIN 1539          // 3 + 3*V
#define NLAY  11            // chained 512x512 GEMMs
#define SA    72            // smem row stride in halfs (64 + 8 pad)

#define ABYTES  (128 * SA * 2)              // 18432
#define STAGE_B (2 * ABYTES)                // 36864
#define TC_SMEM (3 * STAGE_B)               // 110592 -> 2 CTAs/SM

// ---- static scratch ----
__device__ __align__(128) __half g_X  [(size_t)NPTS * KP];
__device__ __align__(128) float  g_P  [(size_t)NPTS * NC];
__device__ __align__(128) __half g_R  [(size_t)NPTS * HID];
__device__ __align__(128) __half g_WcT[(size_t)NC * KP];
__device__ __align__(128) __half g_BT [(size_t)NLAY * HID * HID];
__device__ __align__(128) float  g_bc [NC];
__device__ __align__(128) __half g_A0 [(size_t)NPTS * HID];
__device__ __align__(128) __half g_A1 [(size_t)NPTS * HID];

// ---------------- helpers ----------------
__device__ __forceinline__ uint32_t smem_u32(const void* p) {
    uint32_t a;
    asm("{ .reg .u64 t; cvta.to.shared.u64 t, %1; cvt.u32.u64 %0, t; }" : "=r"(a) : "l"(p));
    return a;
}
#define CP_ASYNC16(dst, src) \
    asm volatile("cp.async.cg.shared.global [%0], [%1], 16;" :: "r"(dst), "l"(src))

#define LDM_X4(r0, r1, r2, r3, addr) \
    asm("ldmatrix.sync.aligned.m8n8.x4.shared.b16 {%0,%1,%2,%3}, [%4];" \
        : "=r"(r0), "=r"(r1), "=r"(r2), "=r"(r3) : "r"(addr) : "memory")

__device__ __forceinline__ void mma16816(float* c, const uint32_t* a, const uint32_t* b) {
    asm("mma.sync.aligned.m16n8k16.row.col.f32.f16.f16.f32 "
        "{%0,%1,%2,%3}, {%4,%5,%6,%7}, {%8,%9}, {%0,%1,%2,%3};"
        : "+f"(c[0]), "+f"(c[1]), "+f"(c[2]), "+f"(c[3])
        : "r"(a[0]), "r"(a[1]), "r"(a[2]), "r"(a[3]), "r"(b[0]), "r"(b[1]));
}

// ---------------------------------------------------------------------------
// Stage 0: warp-per-row 8-NN (shfl-only) + sync-free latent copy
// ---------------------------------------------------------------------------
__global__ void __launch_bounds__(256)
build_x_kernel(const float* __restrict__ cxyz) {
    const int warp = threadIdx.x >> 5, lane = threadIdx.x & 31;
    const int rowBase = blockIdx.x * 8;

    for (int e = threadIdx.x; e < 8 * 3 * NV; e += 256) {
        int rl = e / (3 * NV), j = e % (3 * NV);
        g_X[(size_t)(rowBase + rl) * KP + 27 + j] =
            __float2half_rn(cxyz[(size_t)(rowBase + rl) * ROWIN + 3 + j]);
    }

    const int row = rowBase + warp;
    const float* cr = cxyz + (size_t)row * ROWIN;
    const float x = cr[0], y = cr[1], z = cr[2];

    float d2[16];
#pragma unroll
    for (int j = 0; j < 16; j++) {
        int g = lane + 32 * j;
        float dx = x - cr[3 + 3 * g], dy = y - cr[4 + 3 * g], dz = z - cr[5 + 3 * g];
        d2[j] = dx * dx + dy * dy + dz * dz;
    }

    int idx8[KNN];
#pragma unroll
    for (int s = 0; s < KNN; s++) {
        float bv = INFINITY; int bj = 0;
#pragma unroll
        for (int j = 0; j < 16; j++)
            if (d2[j] < bv) { bv = d2[j]; bj = j; }
        int bidx = lane + 32 * bj;
#pragma unroll
        for (int o = 16; o > 0; o >>= 1) {
            float ov = __shfl_xor_sync(0xffffffffu, bv, o);
            int   oi = __shfl_xor_sync(0xffffffffu, bidx, o);
            if (ov < bv || (ov == bv && oi < bidx)) { bv = ov; bidx = oi; }
        }
        idx8[s] = bidx;
        if ((bidx & 31) == lane) d2[bidx >> 5] = INFINITY;
    }

    __half* xr = g_X + (size_t)row * KP;
    if (lane < 3) xr[lane] = __float2half_rn(cr[lane]);
    if (lane >= 3 && lane < 27) {
        int t = lane - 3;
        xr[lane] = __float2half_rn(cr[3 + 3 * idx8[t / 3] + (t % 3)]);
    }
    for (int t = F0V + lane; t < KP; t += 32) xr[t] = __float2half_rn(0.f);
}

// ---------------------------------------------------------------------------
// Tiled-transpose weight packing (coalesced read AND write via 32x33 smem)
// ---------------------------------------------------------------------------
__global__ void __launch_bounds__(256)
pack_wcT_kernel(const float* __restrict__ Wf, const float* __restrict__ Win) {
    __shared__ float tile[32][33];
    const int k0 = blockIdx.x * 32;          // KP/32 = 50 tiles
    const int n0 = blockIdx.y * 32;          // NC/32 = 64 tiles
    const int tx = threadIdx.x & 31, ty = threadIdx.x >> 5;   // 32 x 8
    const int blk = n0 >> 9;
#pragma unroll
    for (int i = 0; i < 4; i++) {
        int k = k0 + ty + i * 8;
        int h = (n0 & 511) + tx;
        float v = 0.f;
        if (k < F0V) {
            if (blk == 0) v = Wf[(size_t)k * HID + h];
            else          v = Win[(size_t)(blk - 1) * FIV * HID + (size_t)(HID + k) * HID + h];
        }
        tile[ty + i * 8][tx] = v;
    }
    __syncthreads();
#pragma unroll
    for (int i = 0; i < 4; i++) {
        int n = n0 + ty + i * 8;
        g_WcT[(size_t)n * KP + k0 + tx] = __float2half_rn(tile[tx][ty + i * 8]);
    }
}

__global__ void __launch_bounds__(256)
pack_bt_kernel(const float* __restrict__ Wh, const float* __restrict__ Win) {
    __shared__ float tile[32][33];
    const int i  = blockIdx.z;
    const int k0 = blockIdx.x * 32;
    const int n0 = blockIdx.y * 32;
    const int tx = threadIdx.x & 31, ty = threadIdx.x >> 5;
    const float* src;
    if (i % 3 == 2) { int b = i / 3 + 1; src = Win + (size_t)(b - 1) * FIV * HID; }
    else            { int b = i / 3, l = i % 3; src = Wh + (size_t)(b * 2 + l) * HID * HID; }
#pragma unroll
    for (int t = 0; t < 4; t++) {
        int k = k0 + ty + t * 8;
        tile[ty + t * 8][tx] = src[(size_t)k * HID + n0 + tx];
    }
    __syncthreads();
    __half* dst = g_BT + (size_t)i * HID * HID;
#pragma unroll
    for (int t = 0; t < 4; t++) {
        int n = n0 + ty + t * 8;
        dst[(size_t)n * HID + k0 + tx] = __float2half_rn(tile[tx][ty + t * 8]);
    }
}

__global__ void pack_b_kernel(const float* __restrict__ bf, const float* __restrict__ bin) {
    int j = blockIdx.x * blockDim.x + threadIdx.x;
    if (j < NC) {
        int blk = j >> 9, h = j & 511;
        g_bc[j] = (blk == 0) ? bf[h] : bin[(blk - 1) * HID + h];
    }
}

// ---------------------------------------------------------------------------
// fp16 mma.sync GEMM — EXACT R13 configuration (best: 2943us).
//   CTA 128x128, BK=64, 8 warps (2m x 4n), warp tile 64x32, 3-stage cp.async,
//   bulk dep-first LDSM schedule, per-warp kk rotation,
//   per-stage recomputed addressing (low register pressure; no spills).
// ---------------------------------------------------------------------------
__global__ void __launch_bounds__(256, 2)
hgemm(const __half* __restrict__ A, int lda,
      const __half* __restrict__ Bt, int ldb,
      const float* __restrict__ addp, int addIsMat, int ldadd,
      void* __restrict__ Yv, int ldy, int outF32,
      __half* __restrict__ Y2,
      int nk, int doRelu)
{
    extern __shared__ __align__(16) char smem[];
    const uint32_t sbase = smem_u32(smem);
    const int tid = threadIdx.x;
    const int m0 = blockIdx.y * 128, n0 = blockIdx.x * 128;
    const int w = tid >> 5, lane = tid & 31;
    const int wm = (w >> 2) * 64, wn = (w & 3) * 32;
    const int kkStart = ((w & 3) + ((w >> 2) << 1)) & 3;

    const __half* Ab0 = A  + (size_t)m0 * lda;
    const __half* Bb0 = Bt + (size_t)n0 * ldb;

    float acc[4][4][4];
#pragma unroll
    for (int i = 0; i < 4; i++)
#pragma unroll
        for (int j = 0; j < 4; j++)
#pragma unroll
            for (int t = 0; t < 4; t++) acc[i][j][t] = 0.f;

    auto load_tile = [&](int s) {
        if (s < nk) {
            uint32_t base = sbase + (s % 3) * STAGE_B;
            const __half* Ag = Ab0 + s * 64;
            const __half* Bg = Bb0 + s * 64;
#pragma unroll
            for (int i = 0; i < 8; i++) {
                int L = tid + i * 256;               // 0..2047
                int ab = L >> 10;                    // 0:A 1:B
                int idx = L & 1023;
                int r = idx >> 3, c = idx & 7;
                const __half* src = (ab ? Bg + (size_t)r * ldb : Ag + (size_t)r * lda) + c * 8;
                CP_ASYNC16(base + ab * ABYTES + r * (SA * 2) + c * 16, src);
            }
        }
        asm volatile("cp.async.commit_group;" ::: "memory");
    };

    load_tile(0);
    load_tile(1);

    const uint32_t lmOff = (uint32_t)((lane & 15) * (SA * 2) + (lane >> 4) * 16);

    for (int s = 0; s < nk; ++s) {
        asm volatile("cp.async.wait_group 1;" ::: "memory");
        __syncthreads();
        load_tile(s + 2);

        const uint32_t stg = sbase + (s % 3) * STAGE_B;
        const uint32_t aB = stg + wm * (SA * 2) + lmOff;
        const uint32_t bB = stg + ABYTES + wn * (SA * 2) + lmOff;
#pragma unroll
        for (int kq = 0; kq < 4; kq++) {
            const int kk = (kq + kkStart) & 3;
            const uint32_t ko = kk * 32;
            uint32_t aF[4][4], bF[4][2];
            LDM_X4(aF[0][0], aF[0][1], aF[0][2], aF[0][3], aB + ko);
            LDM_X4(bF[0][0], bF[1][0], bF[0][1], bF[1][1], bB + ko);
            LDM_X4(bF[2][0], bF[3][0], bF[2][1], bF[3][1], bB + 16 * SA * 2 + ko);
            LDM_X4(aF[1][0], aF[1][1], aF[1][2], aF[1][3], aB + 1 * (16 * SA * 2) + ko);
            LDM_X4(aF[2][0], aF[2][1], aF[2][2], aF[2][3], aB + 2 * (16 * SA * 2) + ko);
            LDM_X4(aF[3][0], aF[3][1], aF[3][2], aF[3][3], aB + 3 * (16 * SA * 2) + ko);
#pragma unroll
            for (int mt = 0; mt < 4; mt++)
#pragma unroll
                for (int nt = 0; nt < 4; nt++)
                    mma16816(acc[mt][nt], aF[mt], bF[nt]);
        }
    }

    // ---- epilogue ----
    float*  Yf = (float*)Yv;
    __half* Yh = (__half*)Yv;
#pragma unroll
    for (int mt = 0; mt < 4; mt++) {
#pragma unroll
        for (int nt = 0; nt < 4; nt++) {
            const float* c = acc[mt][nt];
            int r0 = m0 + wm + mt * 16 + (lane >> 2);
            int cc = n0 + wn + nt * 8 + (lane & 3) * 2;
#pragma unroll
            for (int h = 0; h < 2; h++) {
                int r = r0 + h * 8;
                float v0 = c[2 * h + 0], v1 = c[2 * h + 1];
                if (addIsMat) {
                    float2 a2 = *(const float2*)(addp + (size_t)r * ldadd + cc);
                    v0 += a2.x; v1 += a2.y;
                } else {
                    v0 += addp[cc]; v1 += addp[cc + 1];
                }
                if (doRelu) { v0 = fmaxf(v0, 0.f); v1 = fmaxf(v1, 0.f); }
                if (outF32) {
                    *(float2*)(Yf + (size_t)r * ldy + cc) = make_float2(v0, v1);
                    if (Y2 != nullptr && cc < HID) {
                        __half2 hv = __floats2half2_rn(fmaxf(v0, 0.f), fmaxf(v1, 0.f));
                        *(__half2*)(Y2 + (size_t)r * HID + cc) = hv;
                    }
                } else {
                    *(__half2*)(Yh + (size_t)r * ldy + cc) = __floats2half2_rn(v0, v1);
                }
            }
        }
    }
}

// ---------------------------------------------------------------------------
// Output: out[row] = tanh(dot(x, W_out) + b_out)
// ---------------------------------------------------------------------------
__global__ void out_kernel(const __half* __restrict__ Xin, const float* __restrict__ Wo,
                           const float* __restrict__ bo, float* __restrict__ out) {
    const int row  = blockIdx.x * 8 + (threadIdx.x >> 5);
    const int lane = threadIdx.x & 31;
    const __half2* xr = (const __half2*)(Xin + (size_t)row * HID);
    float s = 0.f;
#pragma unroll 4
    for (int j = lane; j < HID / 2; j += 32) {
        float2 v = __half22float2(xr[j]);
        s += v.x * Wo[2 * j] + v.y * Wo[2 * j + 1];
    }
#pragma unroll
    for (int o = 16; o > 0; o >>= 1) s += __shfl_xor_sync(0xffffffffu, s, o);
    if (lane == 0) out[row] = tanhf(s + bo[0]);
}

// ---------------------------------------------------------------------------
extern "C" void kernel_launch(void* const* d_in, const int* in_sizes, int n_in,
                              void* d_out, int out_size) {
    const float* cxyz = (const float*)d_in[0];
    const float* Wf   = (const float*)d_in[1];
    const float* bf   = (const float*)d_in[2];
    const float* Win  = (const float*)d_in[3];
    const float* bin  = (const float*)d_in[4];
    const float* Wh   = (const float*)d_in[5];
    const float* bh   = (const float*)d_in[6];
    const float* Wo   = (const float*)d_in[7];
    const float* bo   = (const float*)d_in[8];
    float* out = (float*)d_out;

    __half *X, *R, *WcT, *BT, *A0, *A1;
    float *P, *bc;
    cudaGetSymbolAddress((void**)&X,   g_X);
    cudaGetSymbolAddress((void**)&P,   g_P);
    cudaGetSymbolAddress((void**)&R,   g_R);
    cudaGetSymbolAddress((void**)&WcT, g_WcT);
    cudaGetSymbolAddress((void**)&BT,  g_BT);
    cudaGetSymbolAddress((void**)&bc,  g_bc);
    cudaGetSymbolAddress((void**)&A0,  g_A0);
    cudaGetSymbolAddress((void**)&A1,  g_A1);

    cudaFuncSetAttribute(hgemm, cudaFuncAttributeMaxDynamicSharedMemorySize, TC_SMEM);

    // Launch order arranged so the BIG hgemm is the 4th launch (ncu samples #4).
    build_x_kernel<<<NPTS / 8, 256>>>(cxyz);
    {
        dim3 g(KP / 32, NC / 32);
        pack_wcT_kernel<<<g, 256>>>(Wf, Win);
    }
    pack_b_kernel<<<8, 256>>>(bf, bin);

    // Big GEMM: P = x_ @ Wcat + bcat (f32 out); also R = relu(P[:, :512]) fp16
    dim3 gBig(NC / 128, NPTS / 128);
    hgemm<<<gBig, 256, TC_SMEM>>>(X, KP, WcT, KP, bc, 0, 0, P, NC, 1, R, KP / 64, 0);

    {
        dim3 g(HID / 32, HID / 32, NLAY);
        pack_bt_kernel<<<g, 256>>>(Wh, Win);
    }

    // Chain of 11 GEMMs (fp16 activations)
    dim3 gL(HID / 128, NPTS / 128);
    const __half* a_in = R;
    __half* outs[2] = { A0, A1 };
    int pp = 0;
    for (int i = 0; i < NLAY; i++) {
        const __half* Bl = BT + (size_t)i * HID * HID;
        const float* addp;
        int addIsMat, ldadd;
        if (i % 3 == 2) {
            int b = i / 3 + 1;
            addp = P + (size_t)b * HID; addIsMat = 1; ldadd = NC;
        } else {
            int b = i / 3, l = i % 3;
            addp = bh + (size_t)(b * 2 + l) * HID; addIsMat = 0; ldadd = 0;
        }
        __half* y = outs[pp];
        hgemm<<<gL, 256, TC_SMEM>>>(a_in, HID, Bl, HID, addp, addIsMat, ldadd,
                                    y, HID, 0, nullptr, HID / 64, 1);
        a_in = y;
        pp ^= 1;
    }

    out_kernel<<<NPTS / 8, 256>>>(a_in, Wo, bo, out);
}